// round 15
// baseline (speedup 1.0000x reference)
#include <cuda_runtime.h>
#include <cuda_fp16.h>
#include <math.h>

// Problem constants
#define BB 2
#define NN 2048
#define DD 512
#define HH 8
#define DHH 64
#define PP 64

// fp16 scratch
__device__ __half g_xh[BB * NN * DD];          // [m][k]
__device__ __half g_wqh[DD * DD];              // [n][k] (transposed)
__device__ __half g_wkh[DD * DD];
__device__ __half g_wvh[DD * DD];
__device__ __half g_woh[DD * DD];
__device__ __half g_qh[BB * HH * NN * DHH];    // [b,h,n,dh]
__device__ __half g_kh[BB * HH * NN * DHH];    // [b,h,n,dh]
__device__ __half g_vh[BB * HH * DHH * NN];    // [b,h,dh,n]  (transposed)
__device__ __half g_atth[BB * NN * HH * DHH];  // [m][k]

// ---------------------------------------------------------------------------
// helpers
// ---------------------------------------------------------------------------
__device__ __forceinline__ void mma16h(float c[4],
                                       unsigned a0, unsigned a1, unsigned a2, unsigned a3,
                                       unsigned b0, unsigned b1) {
    asm volatile(
        "mma.sync.aligned.m16n8k16.row.col.f32.f16.f16.f32 "
        "{%0,%1,%2,%3}, {%4,%5,%6,%7}, {%8,%9}, {%0,%1,%2,%3};\n"
        : "+f"(c[0]), "+f"(c[1]), "+f"(c[2]), "+f"(c[3])
        : "r"(a0), "r"(a1), "r"(a2), "r"(a3), "r"(b0), "r"(b1));
}
__device__ __forceinline__ unsigned ex2h2(unsigned e) {
    unsigned r;
    asm("ex2.approx.f16x2 %0, %1;" : "=r"(r) : "r"(e));
    return r;
}
__device__ __forceinline__ unsigned packh2(float x, float y) {
    __half2 h = __floats2half2_rn(x, y);
    return *(unsigned*)&h;
}
__device__ __forceinline__ unsigned mulh2(unsigned a, unsigned b) {
    __half2 r = __hmul2(*(__half2*)&a, *(__half2*)&b);
    return *(unsigned*)&r;
}
__device__ __forceinline__ void cp16(unsigned s, const void* g) {
    asm volatile("cp.async.ca.shared.global [%0], [%1], 16;" :: "r"(s), "l"(g));
}
#define CP_COMMIT() asm volatile("cp.async.commit_group;")
#define CP_WAIT0()  asm volatile("cp.async.wait_group 0;")
#define CP_WAIT2()  asm volatile("cp.async.wait_group 2;")
#define LDSM4(r0, r1, r2, r3, addr)                                              \
    asm volatile("ldmatrix.sync.aligned.m8n8.x4.shared.b16 {%0,%1,%2,%3}, [%4];" \
        : "=r"(r0), "=r"(r1), "=r"(r2), "=r"(r3) : "r"(addr))

// ---------------------------------------------------------------------------
// Prep 1: x -> half, [m][k].
// ---------------------------------------------------------------------------
__global__ __launch_bounds__(256) void conv_x(const float* __restrict__ x)
{
    int idx = (blockIdx.x * 256 + threadIdx.x) * 4;
    float4 v = *(const float4*)&x[idx];
    __half2* d = (__half2*)&g_xh[idx];
    d[0] = __floats2half2_rn(v.x, v.y);
    d[1] = __floats2half2_rn(v.z, v.w);
}

// ---------------------------------------------------------------------------
// Prep 2: W[k][n] float -> W_T[n][k] half, tiled transpose. grid (16,16,4).
// ---------------------------------------------------------------------------
__global__ __launch_bounds__(256) void trans_w(
    const float* __restrict__ wq,
    const float* __restrict__ wk,
    const float* __restrict__ wv,
    const float* __restrict__ wo)
{
    __shared__ float tile[32][33];
    const float* W = (blockIdx.z == 0) ? wq : (blockIdx.z == 1) ? wk :
                     (blockIdx.z == 2) ? wv : wo;
    __half* WT = (blockIdx.z == 0) ? g_wqh : (blockIdx.z == 1) ? g_wkh :
                 (blockIdx.z == 2) ? g_wvh : g_woh;
    int tx = threadIdx.x, ty = threadIdx.y;   // 32 x 8
    int k0 = blockIdx.y * 32, n0 = blockIdx.x * 32;
    #pragma unroll
    for (int j = 0; j < 4; j++)
        tile[ty + j * 8][tx] = W[(size_t)(k0 + ty + j * 8) * DD + n0 + tx];
    __syncthreads();
    #pragma unroll
    for (int j = 0; j < 4; j++)
        WT[(size_t)(n0 + ty + j * 8) * DD + k0 + tx] =
            __float2half_rn(tile[tx][ty + j * 8]);
}

// ---------------------------------------------------------------------------
// GEMM: fp16 m16n8k16, CTA 128(m) x 64(n), 8 warps, 4-stage cp.async,
// ldmatrix.x4 fragment loads. (unchanged from R12)
// ---------------------------------------------------------------------------
#define STAGE_A_B (128 * 80)
#define STAGE_B_B (64 * 80)
#define STAGE_BYTES (STAGE_A_B + STAGE_B_B)     // 15360
#define GEMM_SMEM_BYTES (4 * STAGE_BYTES)       // 61440

#define G_LOAD16(Asrc, Bsrc, KT, STG)                                            \
    do {                                                                         \
        unsigned sa = smemBase + (unsigned)((STG) * STAGE_BYTES);                \
        _Pragma("unroll")                                                        \
        for (int i = 0; i < 2; i++) {                                            \
            int f = tid + i * 256;                                               \
            int row = f >> 2, c = f & 3;                                         \
            cp16(sa + (unsigned)(row * 80 + c * 16),                             \
                 &Asrc[(size_t)(rowBase + row) * DD + (KT) + c * 8]);            \
        }                                                                        \
        unsigned sb = sa + STAGE_A_B;                                            \
        {                                                                        \
            int row = tid >> 2, c = tid & 3;                                     \
            cp16(sb + (unsigned)(row * 80 + c * 16),                             \
                 &Bsrc[(size_t)(colBase + row) * DD + (KT) + c * 8]);            \
        }                                                                        \
    } while (0)

#define G_MMA16(STG)                                                             \
    do {                                                                         \
        unsigned stBase = smemBase + (unsigned)((STG) * STAGE_BYTES);            \
        unsigned a[2][2][4];                                                     \
        _Pragma("unroll")                                                        \
        for (int mi = 0; mi < 2; mi++)                                           \
            _Pragma("unroll")                                                    \
            for (int ks = 0; ks < 2; ks++)                                       \
                LDSM4(a[mi][ks][0], a[mi][ks][1], a[mi][ks][2], a[mi][ks][3],    \
                      stBase + aOff[mi] + (unsigned)(ks * 32));                  \
        unsigned bb[4][4];                                                       \
        _Pragma("unroll")                                                        \
        for (int ni = 0; ni < 4; ni++)                                           \
            LDSM4(bb[ni][0], bb[ni][1], bb[ni][2], bb[ni][3],                    \
                  stBase + (unsigned)STAGE_A_B + bOff + (unsigned)(ni * 640));   \
        _Pragma("unroll")                                                        \
        for (int ks = 0; ks < 2; ks++)                                           \
            _Pragma("unroll")                                                    \
            for (int ni = 0; ni < 4; ni++) {                                     \
                mma16h(acc[0][ni], a[0][ks][0], a[0][ks][1], a[0][ks][2], a[0][ks][3], \
                       bb[ni][2 * ks], bb[ni][2 * ks + 1]);                      \
                mma16h(acc[1][ni], a[1][ks][0], a[1][ks][1], a[1][ks][2], a[1][ks][3], \
                       bb[ni][2 * ks], bb[ni][2 * ks + 1]);                      \
            }                                                                    \
    } while (0)

#define G_MAINLOOP16(Asrc, Bsrc)                                                 \
    do {                                                                         \
        G_LOAD16(Asrc, Bsrc, 0, 0);  CP_COMMIT();                                \
        G_LOAD16(Asrc, Bsrc, 32, 1); CP_COMMIT();                                \
        G_LOAD16(Asrc, Bsrc, 64, 2); CP_COMMIT();                                \
        _Pragma("unroll 1")                                                      \
        for (int it = 0; it < DD / 32; it++) {                                   \
            CP_WAIT2();                                                          \
            __syncthreads();                                                     \
            if (it + 3 < DD / 32) G_LOAD16(Asrc, Bsrc, (it + 3) * 32, (it + 3) & 3); \
            CP_COMMIT();                                                         \
            G_MMA16(it & 3);                                                     \
            __syncthreads();                                                     \
        }                                                                        \
    } while (0)

#define G_FRAG_OFFSETS()                                                         \
    unsigned aOff[2];                                                            \
    {                                                                            \
        int laneRow = (lane & 7) + ((lane >> 3) & 1) * 8;                        \
        int chunk = (lane >> 4) & 1;                                             \
        aOff[0] = (unsigned)((wm * 32 + laneRow) * 80 + chunk * 16);             \
        aOff[1] = aOff[0] + 16 * 80;                                             \
    }                                                                            \
    const unsigned bOff = (unsigned)((wn * 32 + (lane & 7)) * 80 + (lane >> 3) * 16)

__global__ __launch_bounds__(256, 3) void qkv_mma(int dummy)
{
    const __half* A = g_xh;
    const __half* B = (blockIdx.z == 0) ? g_wqh : ((blockIdx.z == 1) ? g_wkh : g_wvh);

    extern __shared__ char smem[];
    const unsigned smemBase = (unsigned)__cvta_generic_to_shared(smem);

    const int tid = threadIdx.x;
    const int w = tid >> 5, lane = tid & 31;
    const int g = lane >> 2, t = lane & 3;
    const int wm = w >> 1, wn = w & 1;

    const int rowBase = blockIdx.y * 128;
    const int colBase = blockIdx.x * 64;

    G_FRAG_OFFSETS();
    float acc[2][4][4] = {};

    G_MAINLOOP16(A, B);

    if (blockIdx.z < 2) {
        __half* out = (blockIdx.z == 0) ? g_qh : g_kh;
        #pragma unroll
        for (int mi = 0; mi < 2; mi++) {
            #pragma unroll
            for (int ni = 0; ni < 4; ni++) {
                int gm0 = rowBase + wm * 32 + mi * 16 + g;
                int gn  = colBase + wn * 32 + ni * 8 + 2 * t;
                int h = gn >> 6, dh = gn & 63;
                {
                    int b = gm0 >> 11, n = gm0 & (NN - 1);
                    *(__half2*)&out[(size_t)(((b * HH + h) * NN) + n) * DHH + dh] =
                        __floats2half2_rn(acc[mi][ni][0], acc[mi][ni][1]);
                }
                {
                    int gm1 = gm0 + 8;
                    int b = gm1 >> 11, n = gm1 & (NN - 1);
                    *(__half2*)&out[(size_t)(((b * HH + h) * NN) + n) * DHH + dh] =
                        __floats2half2_rn(acc[mi][ni][2], acc[mi][ni][3]);
                }
            }
        }
    } else {
        #pragma unroll
        for (int mi = 0; mi < 2; mi++) {
            #pragma unroll
            for (int ni = 0; ni < 4; ni++) {
                int gm0 = rowBase + wm * 32 + mi * 16 + g;
                int gm1 = gm0 + 8;
                int gn  = colBase + wn * 32 + ni * 8 + 2 * t;
                int h = gn >> 6, dh = gn & 63;
                int b0 = gm0 >> 11, n0 = gm0 & (NN - 1);
                int b1 = gm1 >> 11, n1 = gm1 & (NN - 1);
                size_t r0 = (size_t)((b0 * HH + h) * DHH);
                size_t r1 = (size_t)((b1 * HH + h) * DHH);
                g_vh[(r0 + dh)     * NN + n0] = __float2half_rn(acc[mi][ni][0]);
                g_vh[(r0 + dh + 1) * NN + n0] = __float2half_rn(acc[mi][ni][1]);
                g_vh[(r1 + dh)     * NN + n1] = __float2half_rn(acc[mi][ni][2]);
                g_vh[(r1 + dh + 1) * NN + n1] = __float2half_rn(acc[mi][ni][3]);
            }
        }
    }
}

__global__ __launch_bounds__(256, 3) void out_mma(
    const float* __restrict__ bo,
    float* __restrict__ y)
{
    extern __shared__ char smem[];
    const unsigned smemBase = (unsigned)__cvta_generic_to_shared(smem);

    const int tid = threadIdx.x;
    const int w = tid >> 5, lane = tid & 31;
    const int g = lane >> 2, t = lane & 3;
    const int wm = w >> 1, wn = w & 1;

    const int rowBase = blockIdx.y * 128;
    const int colBase = blockIdx.x * 64;

    G_FRAG_OFFSETS();
    float acc[2][4][4] = {};

    G_MAINLOOP16(g_atth, g_woh);

    #pragma unroll
    for (int mi = 0; mi < 2; mi++) {
        #pragma unroll
        for (int ni = 0; ni < 4; ni++) {
            int gm0 = rowBase + wm * 32 + mi * 16 + g;
            int gn  = colBase + wn * 32 + ni * 8 + 2 * t;
            float2 bov = *(const float2*)&bo[gn];
            float2 v0; v0.x = acc[mi][ni][0] + bov.x; v0.y = acc[mi][ni][1] + bov.y;
            float2 v1; v1.x = acc[mi][ni][2] + bov.x; v1.y = acc[mi][ni][3] + bov.y;
            *(float2*)&y[(size_t)gm0 * DD + gn] = v0;
            *(float2*)&y[(size_t)(gm0 + 8) * DD + gn] = v1;
        }
    }
}

// ---------------------------------------------------------------------------
// Flash attention: fp16 mma, 128-KEY tiles, cp.async double-buffered,
// ldmatrix frags, f16x2 softmax fused, PV fused per 32-key group.
// K buf: [128 keys][36 u32] stride 144B; V buf: [64 dh][68 u32] stride 272B.
// ---------------------------------------------------------------------------
#define AK_ROW_B 144                    // K row: 36 u32
#define AV_ROW_B 272                    // V row: 68 u32
#define AK_TILE_B (128 * AK_ROW_B)      // 18432
#define AV_TILE_B (64 * AV_ROW_B)       // 17408
#define A_BUF_B (AK_TILE_B + AV_TILE_B) // 35840
#define ATT_SMEM_BYTES (2 * A_BUF_B)    // 71680
#define ONES2 0x3C003C00u               // half2 {1,1}

__global__ __launch_bounds__(256, 2) void attention_mma(
    const float* __restrict__ rel_pos,
    const float* __restrict__ c_emb)
{
    extern __shared__ char sm[];
    __shared__ float relS[132];
    __shared__ float gateS[132];
    const unsigned smBase = (unsigned)__cvta_generic_to_shared(sm);

    const int qb  = blockIdx.x;
    const int h   = blockIdx.y;
    const int b   = blockIdx.z;
    const int tid = threadIdx.x;
    const int w    = tid >> 5;
    const int lane = tid & 31;
    const int g    = lane >> 2;
    const int t    = lane & 3;

    const size_t bh = (size_t)(b * HH + h);
    const __half* kptr = g_kh + bh * NN * DHH;          // [n][dh]
    const __half* vptr = g_vh + bh * DHH * NN;          // [dh][n]

    const int i0 = qb * 128 + w * 16;
    const float sc = 0.125f * 1.4426950408889634f;  // log2(e)/8

    for (int u = tid; u < 129; u += 256) {
        relS[u]  = rel_pos[u * HH + h] * sc;
        gateS[u] = c_emb[u * HH + h];
    }

    // K: 128 rows x 128B (8 chunks) = 1024 cp16; V: 64 rows x 256B (16 chunks) = 1024 cp16
    #define LOAD_KV(KB, BUF)                                                     \
        do {                                                                     \
            unsigned kB = smBase + (unsigned)((BUF) * A_BUF_B);                  \
            _Pragma("unroll")                                                    \
            for (int i = 0; i < 4; i++) {                                        \
                int f = tid + i * 256;                                           \
                int row = f >> 3, c = f & 7;                                     \
                cp16(kB + (unsigned)(row * AK_ROW_B + c * 16),                   \
                     &kptr[(size_t)((KB) + row) * DHH + c * 8]);                 \
            }                                                                    \
            unsigned vB = kB + AK_TILE_B;                                        \
            _Pragma("unroll")                                                    \
            for (int r = 0; r < 4; r++) {                                        \
                int row = tid >> 2;                                              \
                int chunk = (tid & 3) + 4 * r;                                   \
                cp16(vB + (unsigned)(row * AV_ROW_B + chunk * 16),               \
                     &vptr[(size_t)row * NN + (KB) + chunk * 8]);                \
            }                                                                    \
        } while (0)

    // per-lane ldmatrix offsets
    const unsigned lmOffK = (unsigned)((lane & 7) * AK_ROW_B + (lane >> 3) * 16);
    const unsigned lmOffV = (unsigned)((lane & 7) * AV_ROW_B + (lane >> 3) * 16);

    // Q fragments (fp16, unscaled)
    unsigned qa[4][4];
    {
        const unsigned* q0 = (const unsigned*)(g_qh + (bh * NN + i0 + g) * DHH);
        const unsigned* q1 = (const unsigned*)(g_qh + (bh * NN + i0 + g + 8) * DHH);
        #pragma unroll
        for (int kc = 0; kc < 4; kc++) {
            qa[kc][0] = q0[kc * 8 + t];
            qa[kc][1] = q1[kc * 8 + t];
            qa[kc][2] = q0[kc * 8 + t + 4];
            qa[kc][3] = q1[kc * 8 + t + 4];
        }
    }

    LOAD_KV(0, 0);
    CP_COMMIT();

    float rsc[4] = {0.f, 0.f, 0.f, 0.f};   // denominator C-frag
    float o[8][4];
    #pragma unroll
    for (int nt = 0; nt < 8; nt++)
        #pragma unroll
        for (int j = 0; j < 4; j++) o[nt][j] = 0.f;

    #pragma unroll 1
    for (int it = 0; it < NN / 128; it++) {
        const int kb = it * 128;
        const int buf = it & 1;
        const unsigned kTile = smBase + (unsigned)(buf * A_BUF_B);
        const unsigned vTile = kTile + AK_TILE_B;

        CP_WAIT0();
        __syncthreads();
        if (it + 1 < NN / 128) { LOAD_KV(kb + 128, buf ^ 1); CP_COMMIT(); }

        const bool farhi = (kb >= i0 + 79);
        const bool farlo = (kb + 191 <= i0);
        const bool far = farhi || farlo;
        const float cb = farhi ? relS[128]  : relS[0];
        const float cg = farhi ? gateS[128] : gateS[0];
        const unsigned cg2 = packh2(cg, cg);

        // 4 groups of 32 keys: S+softmax (4 nt) then PV for the kc pair
        #pragma unroll
        for (int np2 = 0; np2 < 4; np2++) {
            unsigned pa4[4][2];
            #pragma unroll
            for (int np = 0; np < 2; np++) {
                unsigned pu[2][2];
                #pragma unroll
                for (int k2 = 0; k2 < 2; k2++) {
                    const int nt = np2 * 4 + np * 2 + k2;
                    unsigned kb0, kb1, kb2, kb3, kb4, kb5, kb6, kb7;
                    unsigned a0 = kTile + (unsigned)(nt * 8 * AK_ROW_B) + lmOffK;
                    LDSM4(kb0, kb1, kb2, kb3, a0);
                    LDSM4(kb4, kb5, kb6, kb7, a0 + 64);
                    float c[4] = {0.f, 0.f, 0.f, 0.f};
                    mma16h(c, qa[0][0], qa[0][1], qa[0][2], qa[0][3], kb0, kb1);
                    mma16h(c, qa[1][0], qa[1][1], qa[1][2], qa[1][3], kb2, kb3);
                    mma16h(c, qa[2][0], qa[2][1], qa[2][2], qa[2][3], kb4, kb5);
                    mma16h(c, qa[3][0], qa[3][1], qa[3][2], qa[3][3], kb6, kb7);

                    unsigned g20, g21;
                    float e0, e1, e2, e3;
                    if (far) {
                        e0 = fmaf(c[0], sc, cb);
                        e1 = fmaf(c[1], sc, cb);
                        e2 = fmaf(c[2], sc, cb);
                        e3 = fmaf(c[3], sc, cb);
                        g20 = cg2; g21 = cg2;
                    } else {
                        int j0 = kb + nt * 8 + 2 * t;
                        int d0 = j0 - (i0 + g);
                        int d1 = d0 - 8;
                        int i00 = min(max(d0,     -PP), PP) + PP;
                        int i01 = min(max(d0 + 1, -PP), PP) + PP;
                        int i10 = min(max(d1,     -PP), PP) + PP;
                        int i11 = min(max(d1 + 1, -PP), PP) + PP;
                        e0 = fmaf(c[0], sc, relS[i00]);
                        e1 = fmaf(c[1], sc, relS[i01]);
                        e2 = fmaf(c[2], sc, relS[i10]);
                        e3 = fmaf(c[3], sc, relS[i11]);
                        g20 = packh2(gateS[i00], gateS[i01]);
                        g21 = packh2(gateS[i10], gateS[i11]);
                    }
                    pu[k2][0] = ex2h2(packh2(e0, e1));
                    pu[k2][1] = ex2h2(packh2(e2, e3));
                    pa4[np * 2 + k2][0] = mulh2(pu[k2][0], g20);
                    pa4[np * 2 + k2][1] = mulh2(pu[k2][1], g21);
                }
                mma16h(rsc, pu[0][0], pu[0][1], pu[1][0], pu[1][1], ONES2, ONES2);
            }
            // PV for keys 32*np2 .. 32*np2+31 (kc pair 2np2, 2np2+1)
            #pragma unroll
            for (int nt8 = 0; nt8 < 8; nt8++) {
                unsigned vb0, vb1, vb2, vb3;
                unsigned a0 = vTile + (unsigned)(nt8 * 8 * AV_ROW_B) + lmOffV
                              + (unsigned)(np2 * 64);
                LDSM4(vb0, vb1, vb2, vb3, a0);
                mma16h(o[nt8], pa4[0][0], pa4[0][1], pa4[1][0], pa4[1][1], vb0, vb1);
                mma16h(o[nt8], pa4[2][0], pa4[2][1], pa4[3][0], pa4[3][1], vb2, vb3);
            }
        }
    }

    // Normalize (rsc holds full row sums), store as half
    float inv0 = 1.f / rsc[0], inv1 = 1.f / rsc[2];

    const size_t base = ((size_t)b * NN) * (HH * DHH) + h * DHH;
    const int r0 = i0 + g, r1 = i0 + g + 8;
    #pragma unroll
    for (int nt = 0; nt < 8; nt++) {
        *(__half2*)&g_atth[base + (size_t)r0 * (HH * DHH) + nt * 8 + 2 * t] =
            __floats2half2_rn(o[nt][0] * inv0, o[nt][1] * inv0);
        *(__half2*)&g_atth[base + (size_t)r1 * (HH * DHH) + nt * 8 + 2 * t] =
            __floats2half2_rn(o[nt][2] * inv1, o[nt][3] * inv1);
    }
}

// ---------------------------------------------------------------------------
extern "C" void kernel_launch(void* const* d_in, const int* in_sizes, int n_in,
                              void* d_out, int out_size)
{
    const float* x       = (const float*)d_in[0];
    const float* Wq      = (const float*)d_in[1];
    const float* Wk      = (const float*)d_in[2];
    const float* Wv      = (const float*)d_in[3];
    const float* rel_pos = (const float*)d_in[4];
    const float* c_emb   = (const float*)d_in[5];
    const float* Wo      = (const float*)d_in[6];
    const float* bo      = (const float*)d_in[7];
    float* y             = (float*)d_out;

    conv_x<<<(BB * NN * DD) / 1024, 256>>>(x);
    dim3 gT(16, 16, 4);
    trans_w<<<gT, dim3(32, 8)>>>(Wq, Wk, Wv, Wo);

    cudaFuncSetAttribute(qkv_mma,
                         cudaFuncAttributeMaxDynamicSharedMemorySize,
                         GEMM_SMEM_BYTES);
    cudaFuncSetAttribute(out_mma,
                         cudaFuncAttributeMaxDynamicSharedMemorySize,
                         GEMM_SMEM_BYTES);
    cudaFuncSetAttribute(attention_mma,
                         cudaFuncAttributeMaxDynamicSharedMemorySize,
                         ATT_SMEM_BYTES);

    dim3 gQKV(DD / 64, (BB * NN) / 128, 3);
    qkv_mma<<<gQKV, 256, GEMM_SMEM_BYTES>>>(0);

    dim3 gAtt(NN / 128, HH, BB);
    attention_mma<<<gAtt, 256, ATT_SMEM_BYTES>>>(rel_pos, c_emb);

    dim3 gOut(DD / 64, (BB * NN) / 128);
    out_mma<<<gOut, 256, GEMM_SMEM_BYTES>>>(bo, y);
}

// round 17
// speedup vs baseline: 1.0486x; 1.0486x over previous
#include <cuda_runtime.h>
#include <cuda_fp16.h>
#include <math.h>

// Problem constants
#define BB 2
#define NN 2048
#define DD 512
#define HH 8
#define DHH 64
#define PP 64

// fp16 scratch
__device__ __half g_xh[BB * NN * DD];          // [m][k]
__device__ __half g_wqh[DD * DD];              // [n][k] (transposed)
__device__ __half g_wkh[DD * DD];
__device__ __half g_wvh[DD * DD];
__device__ __half g_woh[DD * DD];
__device__ __half g_qh[BB * HH * NN * DHH];    // [b,h,n,dh]
__device__ __half g_kh[BB * HH * NN * DHH];    // [b,h,n,dh]
__device__ __half g_vh[BB * HH * DHH * NN];    // [b,h,dh,n]  (transposed)
__device__ __half g_atth[BB * NN * HH * DHH];  // [m][k]

// ---------------------------------------------------------------------------
// helpers
// ---------------------------------------------------------------------------
__device__ __forceinline__ void mma16h(float c[4],
                                       unsigned a0, unsigned a1, unsigned a2, unsigned a3,
                                       unsigned b0, unsigned b1) {
    asm volatile(
        "mma.sync.aligned.m16n8k16.row.col.f32.f16.f16.f32 "
        "{%0,%1,%2,%3}, {%4,%5,%6,%7}, {%8,%9}, {%0,%1,%2,%3};\n"
        : "+f"(c[0]), "+f"(c[1]), "+f"(c[2]), "+f"(c[3])
        : "r"(a0), "r"(a1), "r"(a2), "r"(a3), "r"(b0), "r"(b1));
}
__device__ __forceinline__ unsigned ex2h2(unsigned e) {
    unsigned r;
    asm("ex2.approx.f16x2 %0, %1;" : "=r"(r) : "r"(e));
    return r;
}
__device__ __forceinline__ unsigned packh2(float x, float y) {
    __half2 h = __floats2half2_rn(x, y);
    return *(unsigned*)&h;
}
__device__ __forceinline__ unsigned mulh2(unsigned a, unsigned b) {
    __half2 r = __hmul2(*(__half2*)&a, *(__half2*)&b);
    return *(unsigned*)&r;
}
__device__ __forceinline__ void cp16(unsigned s, const void* g) {
    asm volatile("cp.async.ca.shared.global [%0], [%1], 16;" :: "r"(s), "l"(g));
}
#define CP_COMMIT() asm volatile("cp.async.commit_group;")
#define CP_WAIT0()  asm volatile("cp.async.wait_group 0;")
#define CP_WAIT2()  asm volatile("cp.async.wait_group 2;")
#define LDSM4(r0, r1, r2, r3, addr)                                              \
    asm volatile("ldmatrix.sync.aligned.m8n8.x4.shared.b16 {%0,%1,%2,%3}, [%4];" \
        : "=r"(r0), "=r"(r1), "=r"(r2), "=r"(r3) : "r"(addr))

// ---------------------------------------------------------------------------
// Prep 1: x -> half, [m][k].
// ---------------------------------------------------------------------------
__global__ __launch_bounds__(256) void conv_x(const float* __restrict__ x)
{
    int idx = (blockIdx.x * 256 + threadIdx.x) * 4;
    float4 v = *(const float4*)&x[idx];
    __half2* d = (__half2*)&g_xh[idx];
    d[0] = __floats2half2_rn(v.x, v.y);
    d[1] = __floats2half2_rn(v.z, v.w);
}

// ---------------------------------------------------------------------------
// Prep 2: W[k][n] float -> W_T[n][k] half, tiled transpose. grid (16,16,4).
// ---------------------------------------------------------------------------
__global__ __launch_bounds__(256) void trans_w(
    const float* __restrict__ wq,
    const float* __restrict__ wk,
    const float* __restrict__ wv,
    const float* __restrict__ wo)
{
    __shared__ float tile[32][33];
    const float* W = (blockIdx.z == 0) ? wq : (blockIdx.z == 1) ? wk :
                     (blockIdx.z == 2) ? wv : wo;
    __half* WT = (blockIdx.z == 0) ? g_wqh : (blockIdx.z == 1) ? g_wkh :
                 (blockIdx.z == 2) ? g_wvh : g_woh;
    int tx = threadIdx.x, ty = threadIdx.y;   // 32 x 8
    int k0 = blockIdx.y * 32, n0 = blockIdx.x * 32;
    #pragma unroll
    for (int j = 0; j < 4; j++)
        tile[ty + j * 8][tx] = W[(size_t)(k0 + ty + j * 8) * DD + n0 + tx];
    __syncthreads();
    #pragma unroll
    for (int j = 0; j < 4; j++)
        WT[(size_t)(n0 + ty + j * 8) * DD + k0 + tx] =
            __float2half_rn(tile[tx][ty + j * 8]);
}

// ---------------------------------------------------------------------------
// GEMM: fp16 m16n8k16, CTA 128(m) x 64(n), 8 warps, 4-stage cp.async,
// ldmatrix.x4 fragment loads.
// ---------------------------------------------------------------------------
#define STAGE_A_B (128 * 80)
#define STAGE_B_B (64 * 80)
#define STAGE_BYTES (STAGE_A_B + STAGE_B_B)     // 15360
#define GEMM_SMEM_BYTES (4 * STAGE_BYTES)       // 61440

#define G_LOAD16(Asrc, Bsrc, KT, STG)                                            \
    do {                                                                         \
        unsigned sa = smemBase + (unsigned)((STG) * STAGE_BYTES);                \
        _Pragma("unroll")                                                        \
        for (int i = 0; i < 2; i++) {                                            \
            int f = tid + i * 256;                                               \
            int row = f >> 2, c = f & 3;                                         \
            cp16(sa + (unsigned)(row * 80 + c * 16),                             \
                 &Asrc[(size_t)(rowBase + row) * DD + (KT) + c * 8]);            \
        }                                                                        \
        unsigned sb = sa + STAGE_A_B;                                            \
        {                                                                        \
            int row = tid >> 2, c = tid & 3;                                     \
            cp16(sb + (unsigned)(row * 80 + c * 16),                             \
                 &Bsrc[(size_t)(colBase + row) * DD + (KT) + c * 8]);            \
        }                                                                        \
    } while (0)

#define G_MMA16(STG)                                                             \
    do {                                                                         \
        unsigned stBase = smemBase + (unsigned)((STG) * STAGE_BYTES);            \
        unsigned a[2][2][4];                                                     \
        _Pragma("unroll")                                                        \
        for (int mi = 0; mi < 2; mi++)                                           \
            _Pragma("unroll")                                                    \
            for (int ks = 0; ks < 2; ks++)                                       \
                LDSM4(a[mi][ks][0], a[mi][ks][1], a[mi][ks][2], a[mi][ks][3],    \
                      stBase + aOff[mi] + (unsigned)(ks * 32));                  \
        unsigned bb[4][4];                                                       \
        _Pragma("unroll")                                                        \
        for (int ni = 0; ni < 4; ni++)                                           \
            LDSM4(bb[ni][0], bb[ni][1], bb[ni][2], bb[ni][3],                    \
                  stBase + (unsigned)STAGE_A_B + bOff + (unsigned)(ni * 640));   \
        _Pragma("unroll")                                                        \
        for (int ks = 0; ks < 2; ks++)                                           \
            _Pragma("unroll")                                                    \
            for (int ni = 0; ni < 4; ni++) {                                     \
                mma16h(acc[0][ni], a[0][ks][0], a[0][ks][1], a[0][ks][2], a[0][ks][3], \
                       bb[ni][2 * ks], bb[ni][2 * ks + 1]);                      \
                mma16h(acc[1][ni], a[1][ks][0], a[1][ks][1], a[1][ks][2], a[1][ks][3], \
                       bb[ni][2 * ks], bb[ni][2 * ks + 1]);                      \
            }                                                                    \
    } while (0)

#define G_MAINLOOP16(Asrc, Bsrc)                                                 \
    do {                                                                         \
        G_LOAD16(Asrc, Bsrc, 0, 0);  CP_COMMIT();                                \
        G_LOAD16(Asrc, Bsrc, 32, 1); CP_COMMIT();                                \
        G_LOAD16(Asrc, Bsrc, 64, 2); CP_COMMIT();                                \
        _Pragma("unroll 1")                                                      \
        for (int it = 0; it < DD / 32; it++) {                                   \
            CP_WAIT2();                                                          \
            __syncthreads();                                                     \
            if (it + 3 < DD / 32) G_LOAD16(Asrc, Bsrc, (it + 3) * 32, (it + 3) & 3); \
            CP_COMMIT();                                                         \
            G_MMA16(it & 3);                                                     \
            __syncthreads();                                                     \
        }                                                                        \
    } while (0)

#define G_FRAG_OFFSETS()                                                         \
    unsigned aOff[2];                                                            \
    {                                                                            \
        int laneRow = (lane & 7) + ((lane >> 3) & 1) * 8;                        \
        int chunk = (lane >> 4) & 1;                                             \
        aOff[0] = (unsigned)((wm * 32 + laneRow) * 80 + chunk * 16);             \
        aOff[1] = aOff[0] + 16 * 80;                                             \
    }                                                                            \
    const unsigned bOff = (unsigned)((wn * 32 + (lane & 7)) * 80 + (lane >> 3) * 16)

// V transpose staging tile: [64 dh][136 n] halves (272B rows: 16B-aligned)
#define VT_STRIDE 136

__global__ __launch_bounds__(256, 3) void qkv_mma(int dummy)
{
    const __half* A = g_xh;
    const __half* B = (blockIdx.z == 0) ? g_wqh : ((blockIdx.z == 1) ? g_wkh : g_wvh);

    extern __shared__ char smem[];
    const unsigned smemBase = (unsigned)__cvta_generic_to_shared(smem);

    const int tid = threadIdx.x;
    const int w = tid >> 5, lane = tid & 31;
    const int g = lane >> 2, t = lane & 3;
    const int wm = w >> 1, wn = w & 1;

    const int rowBase = blockIdx.y * 128;
    const int colBase = blockIdx.x * 64;

    G_FRAG_OFFSETS();
    float acc[2][4][4] = {};

    G_MAINLOOP16(A, B);

    if (blockIdx.z < 2) {
        __half* out = (blockIdx.z == 0) ? g_qh : g_kh;
        #pragma unroll
        for (int mi = 0; mi < 2; mi++) {
            #pragma unroll
            for (int ni = 0; ni < 4; ni++) {
                int gm0 = rowBase + wm * 32 + mi * 16 + g;
                int gn  = colBase + wn * 32 + ni * 8 + 2 * t;
                int h = gn >> 6, dh = gn & 63;
                {
                    int b = gm0 >> 11, n = gm0 & (NN - 1);
                    *(__half2*)&out[(size_t)(((b * HH + h) * NN) + n) * DHH + dh] =
                        __floats2half2_rn(acc[mi][ni][0], acc[mi][ni][1]);
                }
                {
                    int gm1 = gm0 + 8;
                    int b = gm1 >> 11, n = gm1 & (NN - 1);
                    *(__half2*)&out[(size_t)(((b * HH + h) * NN) + n) * DHH + dh] =
                        __floats2half2_rn(acc[mi][ni][2], acc[mi][ni][3]);
                }
            }
        }
    } else {
        // V: stage transposed tile in smem, then coalesced float4 stores to
        // g_vh[b,h,dh,n]. CTA covers one head (colBase is 64-aligned) and one b.
        __half* vt = (__half*)smem;   // [64][VT_STRIDE]
        #pragma unroll
        for (int mi = 0; mi < 2; mi++) {
            #pragma unroll
            for (int ni = 0; ni < 4; ni++) {
                int ml0 = wm * 32 + mi * 16 + g;        // local m (n-position)
                int nl  = wn * 32 + ni * 8 + 2 * t;     // local n (dh)
                vt[(nl)     * VT_STRIDE + ml0] = __float2half_rn(acc[mi][ni][0]);
                vt[(nl + 1) * VT_STRIDE + ml0] = __float2half_rn(acc[mi][ni][1]);
                vt[(nl)     * VT_STRIDE + ml0 + 8] = __float2half_rn(acc[mi][ni][2]);
                vt[(nl + 1) * VT_STRIDE + ml0 + 8] = __float2half_rn(acc[mi][ni][3]);
            }
        }
        __syncthreads();
        const int b = rowBase >> 11;
        const int h = colBase >> 6;
        const int nb = rowBase & (NN - 1);
        __half* dst = g_vh + (size_t)((b * HH + h) * DHH) * NN + nb;
        // 64 rows x 128 halves = 1024 float4 chunks; 4 per thread
        #pragma unroll
        for (int i = 0; i < 4; i++) {
            int f = tid + i * 256;
            int dh = f >> 4, c8 = (f & 15) << 3;
            float4 v4 = *(const float4*)&vt[dh * VT_STRIDE + c8];
            *(float4*)&dst[(size_t)dh * NN + c8] = v4;
        }
    }
}

__global__ __launch_bounds__(256, 3) void out_mma(
    const float* __restrict__ bo,
    float* __restrict__ y)
{
    extern __shared__ char smem[];
    const unsigned smemBase = (unsigned)__cvta_generic_to_shared(smem);

    const int tid = threadIdx.x;
    const int w = tid >> 5, lane = tid & 31;
    const int g = lane >> 2, t = lane & 3;
    const int wm = w >> 1, wn = w & 1;

    const int rowBase = blockIdx.y * 128;
    const int colBase = blockIdx.x * 64;

    G_FRAG_OFFSETS();
    float acc[2][4][4] = {};

    G_MAINLOOP16(g_atth, g_woh);

    #pragma unroll
    for (int mi = 0; mi < 2; mi++) {
        #pragma unroll
        for (int ni = 0; ni < 4; ni++) {
            int gm0 = rowBase + wm * 32 + mi * 16 + g;
            int gn  = colBase + wn * 32 + ni * 8 + 2 * t;
            float2 bov = *(const float2*)&bo[gn];
            float2 v0; v0.x = acc[mi][ni][0] + bov.x; v0.y = acc[mi][ni][1] + bov.y;
            float2 v1; v1.x = acc[mi][ni][2] + bov.x; v1.y = acc[mi][ni][3] + bov.y;
            *(float2*)&y[(size_t)gm0 * DD + gn] = v0;
            *(float2*)&y[(size_t)(gm0 + 8) * DD + gn] = v1;
        }
    }
}

// ---------------------------------------------------------------------------
// Flash attention (R12-proven): fp16 mma, 64-key tiles, cp.async double-
// buffered, ldmatrix frags, f16x2 softmax fused into S-phase, denom via
// P*ones mma. No online max (logits bounded).
// ---------------------------------------------------------------------------
#define KV_ROW_B 144                    // 36 u32
#define KV_TILE_B (64 * KV_ROW_B)       // 9216
#define ATT_BUF_B (2 * KV_TILE_B)       // K+V per buffer
#define ONES2 0x3C003C00u               // half2 {1,1}

__global__ __launch_bounds__(256, 2) void attention_mma(
    const float* __restrict__ rel_pos,
    const float* __restrict__ c_emb)
{
    __shared__ char sm[2 * ATT_BUF_B];
    __shared__ float relS[132];
    __shared__ float gateS[132];
    const unsigned smBase = (unsigned)__cvta_generic_to_shared(sm);

    const int qb  = blockIdx.x;
    const int h   = blockIdx.y;
    const int b   = blockIdx.z;
    const int tid = threadIdx.x;
    const int w    = tid >> 5;
    const int lane = tid & 31;
    const int g    = lane >> 2;
    const int t    = lane & 3;

    const size_t bh = (size_t)(b * HH + h);
    const __half* kptr = g_kh + bh * NN * DHH;          // [n][dh]
    const __half* vptr = g_vh + bh * DHH * NN;          // [dh][n]

    const int i0 = qb * 128 + w * 16;
    const float sc = 0.125f * 1.4426950408889634f;  // log2(e)/8

    for (int u = tid; u < 129; u += 256) {
        relS[u]  = rel_pos[u * HH + h] * sc;
        gateS[u] = c_emb[u * HH + h];
    }

    #define LOAD_KV(KB, BUF)                                                     \
        do {                                                                     \
            unsigned kB = smBase + (unsigned)((BUF) * ATT_BUF_B);                \
            unsigned vB = kB + KV_TILE_B;                                        \
            _Pragma("unroll")                                                    \
            for (int r = 0; r < 2; r++) {                                        \
                int row = r * 32 + (tid >> 3);                                   \
                int c = tid & 7;                                                 \
                cp16(kB + (unsigned)(row * KV_ROW_B + c * 16),                   \
                     &kptr[(size_t)((KB) + row) * DHH + c * 8]);                 \
                cp16(vB + (unsigned)(row * KV_ROW_B + c * 16),                   \
                     &vptr[(size_t)row * NN + (KB) + c * 8]);                    \
            }                                                                    \
        } while (0)

    // per-lane ldmatrix offset: row (lane&7), tile (lane>>3)
    const unsigned lmOff = (unsigned)((lane & 7) * KV_ROW_B + (lane >> 3) * 16);

    // Q fragments (fp16, unscaled)
    unsigned qa[4][4];
    {
        const unsigned* q0 = (const unsigned*)(g_qh + (bh * NN + i0 + g) * DHH);
        const unsigned* q1 = (const unsigned*)(g_qh + (bh * NN + i0 + g + 8) * DHH);
        #pragma unroll
        for (int kc = 0; kc < 4; kc++) {
            qa[kc][0] = q0[kc * 8 + t];
            qa[kc][1] = q1[kc * 8 + t];
            qa[kc][2] = q0[kc * 8 + t + 4];
            qa[kc][3] = q1[kc * 8 + t + 4];
        }
    }

    LOAD_KV(0, 0);
    CP_COMMIT();

    float rsc[4] = {0.f, 0.f, 0.f, 0.f};   // denominator C-frag
    float o[8][4];
    #pragma unroll
    for (int nt = 0; nt < 8; nt++)
        #pragma unroll
        for (int j = 0; j < 4; j++) o[nt][j] = 0.f;

    #pragma unroll 1
    for (int it = 0; it < NN / 64; it++) {
        const int kb = it * 64;
        const int buf = it & 1;
        const unsigned kTile = smBase + (unsigned)(buf * ATT_BUF_B);
        const unsigned vTile = kTile + KV_TILE_B;

        CP_WAIT0();
        __syncthreads();
        if (it + 1 < NN / 64) { LOAD_KV(kb + 64, buf ^ 1); CP_COMMIT(); }

        const bool farhi = (kb >= i0 + 79);
        const bool farlo = (kb + 127 <= i0);
        const bool far = farhi || farlo;
        const float cb = farhi ? relS[128]  : relS[0];
        const float cg = farhi ? gateS[128] : gateS[0];
        const unsigned cg2 = packh2(cg, cg);

        // Fused S + softmax
        unsigned pa[8][2];
        #pragma unroll
        for (int np = 0; np < 4; np++) {
            unsigned pu[2][2];
            #pragma unroll
            for (int k2 = 0; k2 < 2; k2++) {
                const int nt = np * 2 + k2;
                unsigned kb0, kb1, kb2, kb3, kb4, kb5, kb6, kb7;
                unsigned a0 = kTile + (unsigned)(nt * 8 * KV_ROW_B) + lmOff;
                LDSM4(kb0, kb1, kb2, kb3, a0);
                LDSM4(kb4, kb5, kb6, kb7, a0 + 64);
                float c[4] = {0.f, 0.f, 0.f, 0.f};
                mma16h(c, qa[0][0], qa[0][1], qa[0][2], qa[0][3], kb0, kb1);
                mma16h(c, qa[1][0], qa[1][1], qa[1][2], qa[1][3], kb2, kb3);
                mma16h(c, qa[2][0], qa[2][1], qa[2][2], qa[2][3], kb4, kb5);
                mma16h(c, qa[3][0], qa[3][1], qa[3][2], qa[3][3], kb6, kb7);

                unsigned g20, g21;
                float e0, e1, e2, e3;
                if (far) {
                    e0 = fmaf(c[0], sc, cb);
                    e1 = fmaf(c[1], sc, cb);
                    e2 = fmaf(c[2], sc, cb);
                    e3 = fmaf(c[3], sc, cb);
                    g20 = cg2; g21 = cg2;
                } else {
                    int j0 = kb + nt * 8 + 2 * t;
                    int d0 = j0 - (i0 + g);
                    int d1 = d0 - 8;
                    int i00 = min(max(d0,     -PP), PP) + PP;
                    int i01 = min(max(d0 + 1, -PP), PP) + PP;
                    int i10 = min(max(d1,     -PP), PP) + PP;
                    int i11 = min(max(d1 + 1, -PP), PP) + PP;
                    e0 = fmaf(c[0], sc, relS[i00]);
                    e1 = fmaf(c[1], sc, relS[i01]);
                    e2 = fmaf(c[2], sc, relS[i10]);
                    e3 = fmaf(c[3], sc, relS[i11]);
                    g20 = packh2(gateS[i00], gateS[i01]);
                    g21 = packh2(gateS[i10], gateS[i11]);
                }
                pu[k2][0] = ex2h2(packh2(e0, e1));
                pu[k2][1] = ex2h2(packh2(e2, e3));
                pa[nt][0] = mulh2(pu[k2][0], g20);
                pa[nt][1] = mulh2(pu[k2][1], g21);
            }
            mma16h(rsc, pu[0][0], pu[0][1], pu[1][0], pu[1][1], ONES2, ONES2);
        }

        // O += P V
        #pragma unroll
        for (int nt = 0; nt < 8; nt++) {
            unsigned vb0, vb1, vb2, vb3, vb4, vb5, vb6, vb7;
            unsigned a0 = vTile + (unsigned)(nt * 8 * KV_ROW_B) + lmOff;
            LDSM4(vb0, vb1, vb2, vb3, a0);
            LDSM4(vb4, vb5, vb6, vb7, a0 + 64);
            mma16h(o[nt], pa[0][0], pa[0][1], pa[1][0], pa[1][1], vb0, vb1);
            mma16h(o[nt], pa[2][0], pa[2][1], pa[3][0], pa[3][1], vb2, vb3);
            mma16h(o[nt], pa[4][0], pa[4][1], pa[5][0], pa[5][1], vb4, vb5);
            mma16h(o[nt], pa[6][0], pa[6][1], pa[7][0], pa[7][1], vb6, vb7);
        }
    }

    float inv0 = 1.f / rsc[0], inv1 = 1.f / rsc[2];

    const size_t base = ((size_t)b * NN) * (HH * DHH) + h * DHH;
    const int r0 = i0 + g, r1 = i0 + g + 8;
    #pragma unroll
    for (int nt = 0; nt < 8; nt++) {
        *(__half2*)&g_atth[base + (size_t)r0 * (HH * DHH) + nt * 8 + 2 * t] =
            __floats2half2_rn(o[nt][0] * inv0, o[nt][1] * inv0);
        *(__half2*)&g_atth[base + (size_t)r1 * (HH * DHH) + nt * 8 + 2 * t] =
            __floats2half2_rn(o[nt][2] * inv1, o[nt][3] * inv1);
    }
}

// ---------------------------------------------------------------------------
extern "C" void kernel_launch(void* const* d_in, const int* in_sizes, int n_in,
                              void* d_out, int out_size)
{
    const float* x       = (const float*)d_in[0];
    const float* Wq      = (const float*)d_in[1];
    const float* Wk      = (const float*)d_in[2];
    const float* Wv      = (const float*)d_in[3];
    const float* rel_pos = (const float*)d_in[4];
    const float* c_emb   = (const float*)d_in[5];
    const float* Wo      = (const float*)d_in[6];
    const float* bo      = (const float*)d_in[7];
    float* y             = (float*)d_out;

    conv_x<<<(BB * NN * DD) / 1024, 256>>>(x);
    dim3 gT(16, 16, 4);
    trans_w<<<gT, dim3(32, 8)>>>(Wq, Wk, Wv, Wo);

    cudaFuncSetAttribute(qkv_mma,
                         cudaFuncAttributeMaxDynamicSharedMemorySize,
                         GEMM_SMEM_BYTES);
    cudaFuncSetAttribute(out_mma,
                         cudaFuncAttributeMaxDynamicSharedMemorySize,
                         GEMM_SMEM_BYTES);

    dim3 gQKV(DD / 64, (BB * NN) / 128, 3);
    qkv_mma<<<gQKV, 256, GEMM_SMEM_BYTES>>>(0);

    dim3 gAtt(NN / 128, HH, BB);
    attention_mma<<<gAtt, 256>>>(rel_pos, c_emb);

    dim3 gOut(DD / 64, (BB * NN) / 128);
    out_mma<<<gOut, 256, GEMM_SMEM_BYTES>>>(bo, y);
}